// round 6
// baseline (speedup 1.0000x reference)
#include <cuda_runtime.h>
#include <math.h>

// Problem constants (fixed by the reference)
#define IMG_W 256
#define IMG_H 256
#define MAXN  512
#define HW    (IMG_W * IMG_H)        // 65536
#define FX    256.0f                  // W / (2 * tanfovx)
#define FY    256.0f
#define LIMX  0.65f                   // 1.3 * tanfovx
#define LIMY  0.65f

#define TILE_W 32
#define TILE_H 16
#define NTHREADS 512                  // TILE_W * TILE_H

// Transmittance early-out: remaining contributions are bounded by T_EPS,
// giving relative error ~3e-5 against the 1e-3 pass threshold.
#define T_EPS 1e-5f

// Output layout in d_out (float32): color [3*HW], radii [MAXN], invd [HW]
#define OFF_RADII (3 * HW)
#define OFF_INVD  (3 * HW + MAXN)

// Blend core: 48 bytes = 3 float4
//   f0 = (px, py, ca, cb)   f1 = (cc, op, cr, cg)   f2 = (cbl, invd, 0, 0)
struct __align__(16) GCore { float4 f0, f1, f2; };

// ---------------------------------------------------------------------------
// Single fused kernel: every CTA redundantly preps all N gaussians (1/thread),
// culls against its own 32x16 tile into shared, rank-sorts the survivors by
// (depth, index) so compositing order is bit-identical to argsort(depth),
// then alpha-blends per pixel from shared with a 4-wide unrolled loop and a
// warp-uniform transmittance early-out.
// ---------------------------------------------------------------------------
__global__ __launch_bounds__(NTHREADS)
void fused_raster_kernel(const float* __restrict__ means3D,
                         const float* __restrict__ opac,
                         const float* __restrict__ colors,
                         const float* __restrict__ scales,
                         const float* __restrict__ rots,
                         const float* __restrict__ Vm,   // 4x4 row-major
                         const float* __restrict__ Pm,   // 4x4 row-major
                         const float* __restrict__ bg,
                         const float* __restrict__ mask,
                         float* __restrict__ out,
                         int n)
{
    __shared__ int                s_cnt;
    __shared__ unsigned long long s_key[MAXN];   // (depth_bits<<32)|gid
    __shared__ GCore              s_core[MAXN];
    __shared__ unsigned short     s_ord[MAXN + 4];

    const int t = threadIdx.x;
    if (t == 0) s_cnt = 0;
    __syncthreads();

    const float tx0 = (float)(blockIdx.x * TILE_W);
    const float tx1 = tx0 + (float)(TILE_W - 1);
    const float ty0 = (float)(blockIdx.y * TILE_H);
    const float ty1 = ty0 + (float)(TILE_H - 1);

    // ---- per-gaussian preprocess (thread t -> gaussian t) ----
    bool push = false;
    float depth = 0.0f, radii_val = 0.0f;
    float px = 0.f, py = 0.f, ca = 0.f, cbv = 0.f, cc = 0.f, op = 0.f;

    if (t < n) {
        const float m0 = means3D[3 * t + 0];
        const float m1 = means3D[3 * t + 1];
        const float m2 = means3D[3 * t + 2];

        // view transform t = V * [m,1]
        const float v0 = Vm[0] * m0 + Vm[1] * m1 + Vm[2]  * m2 + Vm[3];
        const float v1 = Vm[4] * m0 + Vm[5] * m1 + Vm[6]  * m2 + Vm[7];
        const float v2 = Vm[8] * m0 + Vm[9] * m1 + Vm[10] * m2 + Vm[11];
        depth = v2;

        // clip = P * [m,1]
        const float c0 = Pm[0]  * m0 + Pm[1]  * m1 + Pm[2]  * m2 + Pm[3];
        const float c1 = Pm[4]  * m0 + Pm[5]  * m1 + Pm[6]  * m2 + Pm[7];
        const float c3 = Pm[12] * m0 + Pm[13] * m1 + Pm[14] * m2 + Pm[15];
        const float pw = 1.0f / (c3 + 1e-7f);
        px = ((c0 * pw + 1.0f) * (float)IMG_W - 1.0f) * 0.5f;
        py = ((c1 * pw + 1.0f) * (float)IMG_H - 1.0f) * 0.5f;

        // quaternion -> rotation (one vectorized load)
        const float4 q4 = *reinterpret_cast<const float4*>(&rots[4 * t]);
        const float qn = rsqrtf(q4.x*q4.x + q4.y*q4.y + q4.z*q4.z + q4.w*q4.w);
        const float w = q4.x * qn, x = q4.y * qn, y = q4.z * qn, z = q4.w * qn;

        const float r00 = 1.0f - 2.0f * (y*y + z*z);
        const float r01 = 2.0f * (x*y - w*z);
        const float r02 = 2.0f * (x*z + w*y);
        const float r10 = 2.0f * (x*y + w*z);
        const float r11 = 1.0f - 2.0f * (x*x + z*z);
        const float r12 = 2.0f * (y*z - w*x);
        const float r20 = 2.0f * (x*z - w*y);
        const float r21 = 2.0f * (y*z + w*x);
        const float r22 = 1.0f - 2.0f * (x*x + y*y);

        const float s0 = scales[3 * t + 0];
        const float s1 = scales[3 * t + 1];
        const float s2 = scales[3 * t + 2];

        // M = R * diag(s); cov3d = M M^T (symmetric)
        const float M00 = r00*s0, M01 = r01*s1, M02 = r02*s2;
        const float M10 = r10*s0, M11 = r11*s1, M12 = r12*s2;
        const float M20 = r20*s0, M21 = r21*s1, M22 = r22*s2;
        const float C00 = M00*M00 + M01*M01 + M02*M02;
        const float C01 = M00*M10 + M01*M11 + M02*M12;
        const float C02 = M00*M20 + M01*M21 + M02*M22;
        const float C11 = M10*M10 + M11*M11 + M12*M12;
        const float C12 = M10*M20 + M11*M21 + M12*M22;
        const float C22 = M20*M20 + M21*M21 + M22*M22;

        // Jacobian
        const float tz = depth;
        const float itz = 1.0f / tz;
        const float txc = fminf(fmaxf(v0 * itz, -LIMX), LIMX) * tz;
        const float tyc = fminf(fmaxf(v1 * itz, -LIMY), LIMY) * tz;
        const float j00 = FX * itz;
        const float j02 = -FX * txc * itz * itz;
        const float j11 = FY * itz;
        const float j12 = -FY * tyc * itz * itz;

        // Tm = J * V[:3,:3]  (rows 0,1 only)
        const float T00 = j00 * Vm[0] + j02 * Vm[8];
        const float T01 = j00 * Vm[1] + j02 * Vm[9];
        const float T02 = j00 * Vm[2] + j02 * Vm[10];
        const float T10 = j11 * Vm[4] + j12 * Vm[8];
        const float T11 = j11 * Vm[5] + j12 * Vm[9];
        const float T12 = j11 * Vm[6] + j12 * Vm[10];

        // cov2d = Tm * C * Tm^T
        const float u0 = C00*T00 + C01*T01 + C02*T02;
        const float u1 = C01*T00 + C11*T01 + C12*T02;
        const float u2 = C02*T00 + C12*T01 + C22*T02;
        const float cxx = T00*u0 + T01*u1 + T02*u2;
        const float cxy = T10*u0 + T11*u1 + T12*u2;
        const float w0 = C00*T10 + C01*T11 + C02*T12;
        const float w1 = C01*T10 + C11*T11 + C12*T12;
        const float w2 = C02*T10 + C12*T11 + C22*T12;
        const float cyy = T10*w0 + T11*w1 + T12*w2;

        const float a = cxx + 0.3f;
        const float b = cxy;
        const float c = cyy + 0.3f;
        const float det = a * c - b * b;
        const float inv_det = 1.0f / ((det != 0.0f) ? det : 1.0f);
        ca  = c * inv_det;
        cbv = -b * inv_det;
        cc  = a * inv_det;
        const float mid = 0.5f * (a + c);
        const float lam = mid + sqrtf(fmaxf(mid * mid - det, 0.1f));
        radii_val = ceilf(3.0f * sqrtf(lam));

        const bool valid = (depth > 0.2f) && (det > 0.0f);
        op = opac[t];

        // keep (alpha>=1/255, power<=0) => mahal^2 <= qmax = 2*ln(255*op);
        // extent along x is sqrt(qmax*a), along y sqrt(qmax*c) (conic det
        // identity). +1 px slack; exact tests run per pixel.
        const float qmax = 2.0f * logf(255.0f * op);
        if (valid && qmax > 0.0f) {
            const float dxm = sqrtf(qmax * a) + 1.0f;
            const float dym = sqrtf(qmax * c) + 1.0f;
            push = (px + dxm >= tx0) && (px - dxm <= tx1) &&
                   (py + dym >= ty0) && (py - dym <= ty1);
        }
    }

    // ---- ballot compaction of this tile's survivors into shared ----
    const unsigned m = __ballot_sync(0xffffffffu, push);
    const int lane = t & 31;
    int wbase = 0;
    if (lane == 0 && m) wbase = atomicAdd(&s_cnt, __popc(m));
    wbase = __shfl_sync(0xffffffffu, wbase, 0);
    if (push) {
        const int pos = wbase + __popc(m & ((1u << lane) - 1u));
        s_key[pos] = ((unsigned long long)__float_as_uint(depth) << 32)
                   | (unsigned long long)t;
        GCore gc;
        gc.f0 = make_float4(px, py, ca, cbv);
        gc.f1 = make_float4(cc, op, colors[3 * t + 0], colors[3 * t + 1]);
        gc.f2 = make_float4(colors[3 * t + 2], 1.0f / fmaxf(depth, 1e-6f),
                            0.0f, 0.0f);
        s_core[pos] = gc;
    }

    // radii output (identical in every CTA; block (0,0) writes)
    if (blockIdx.x == 0 && blockIdx.y == 0 && t < n)
        out[OFF_RADII + t] = radii_val;

    __syncthreads();
    const int cnt = s_cnt;

    // ---- rank-sort survivors by unique (depth_bits, gid) key ----
    for (int i = t; i < cnt; i += NTHREADS) {
        const unsigned long long k = s_key[i];
        int r = 0;
        for (int j = 0; j < cnt; j++) r += (s_key[j] < k);
        s_ord[r] = (unsigned short)i;
    }
    // pad so the unrolled loop's ushort4 load is always in-bounds
    if (t < 4) s_ord[cnt + t] = 0;
    __syncthreads();

    // ---- per-pixel front-to-back blend, 4-wide unrolled + early-out ----
    const int pxi = blockIdx.x * TILE_W + (t & (TILE_W - 1));
    const int pyi = blockIdx.y * TILE_H + (t / TILE_W);
    const float xf = (float)pxi;
    const float yf = (float)pyi;

    float Tacc = 1.0f;
    float cr = 0.0f, cg = 0.0f, cbl = 0.0f, iv = 0.0f;

    int j = 0;
    const int cnt4 = cnt & ~3;
    for (; j < cnt4; j += 4) {
        // warp-uniform transmittance early-out: remaining terms each carry a
        // factor Tacc < T_EPS -> bounded ~1e-5 absolute error.
        if (__all_sync(0xffffffffu, Tacc < T_EPS))
            break;

        // 4 indices in one 64-bit LDS (j is 4-aligned, s_ord padded)
        const ushort4 o4 = *reinterpret_cast<const ushort4*>(&s_ord[j]);

        const GCore g0 = s_core[o4.x];
        const GCore g1 = s_core[o4.y];
        const GCore g2 = s_core[o4.z];
        const GCore g3 = s_core[o4.w];

        // independent alpha computations (masked to 0 when keep tests fail)
        float al[4];
        {
            const float dx = xf - g0.f0.x, dy = yf - g0.f0.y;
            const float p = -0.5f * (g0.f0.z*dx*dx + g0.f1.x*dy*dy) - g0.f0.w*dx*dy;
            const float a = fminf(0.99f, g0.f1.y * __expf(p));
            al[0] = (p <= 0.0f && a >= (1.0f/255.0f)) ? a : 0.0f;
        }
        {
            const float dx = xf - g1.f0.x, dy = yf - g1.f0.y;
            const float p = -0.5f * (g1.f0.z*dx*dx + g1.f1.x*dy*dy) - g1.f0.w*dx*dy;
            const float a = fminf(0.99f, g1.f1.y * __expf(p));
            al[1] = (p <= 0.0f && a >= (1.0f/255.0f)) ? a : 0.0f;
        }
        {
            const float dx = xf - g2.f0.x, dy = yf - g2.f0.y;
            const float p = -0.5f * (g2.f0.z*dx*dx + g2.f1.x*dy*dy) - g2.f0.w*dx*dy;
            const float a = fminf(0.99f, g2.f1.y * __expf(p));
            al[2] = (p <= 0.0f && a >= (1.0f/255.0f)) ? a : 0.0f;
        }
        {
            const float dx = xf - g3.f0.x, dy = yf - g3.f0.y;
            const float p = -0.5f * (g3.f0.z*dx*dx + g3.f1.x*dy*dy) - g3.f0.w*dx*dy;
            const float a = fminf(0.99f, g3.f1.y * __expf(p));
            al[3] = (p <= 0.0f && a >= (1.0f/255.0f)) ? a : 0.0f;
        }

        // short serial accumulate (alpha==0 is an exact no-op)
        float wgt;
        wgt = al[0] * Tacc;
        cr += wgt * g0.f1.z; cg += wgt * g0.f1.w;
        cbl += wgt * g0.f2.x; iv += wgt * g0.f2.y;
        Tacc *= (1.0f - al[0]);
        wgt = al[1] * Tacc;
        cr += wgt * g1.f1.z; cg += wgt * g1.f1.w;
        cbl += wgt * g1.f2.x; iv += wgt * g1.f2.y;
        Tacc *= (1.0f - al[1]);
        wgt = al[2] * Tacc;
        cr += wgt * g2.f1.z; cg += wgt * g2.f1.w;
        cbl += wgt * g2.f2.x; iv += wgt * g2.f2.y;
        Tacc *= (1.0f - al[2]);
        wgt = al[3] * Tacc;
        cr += wgt * g3.f1.z; cg += wgt * g3.f1.w;
        cbl += wgt * g3.f2.x; iv += wgt * g3.f2.y;
        Tacc *= (1.0f - al[3]);
    }
    if (!__all_sync(0xffffffffu, Tacc < T_EPS)) {
        for (; j < cnt; j++) {
            const GCore& g = s_core[s_ord[j]];
            const float dx = xf - g.f0.x, dy = yf - g.f0.y;
            const float p = -0.5f * (g.f0.z*dx*dx + g.f1.x*dy*dy) - g.f0.w*dx*dy;
            if (p <= 0.0f) {
                const float a = fminf(0.99f, g.f1.y * __expf(p));
                if (a >= (1.0f/255.0f)) {
                    const float wgt = a * Tacc;
                    cr += wgt * g.f1.z; cg += wgt * g.f1.w;
                    cbl += wgt * g.f2.x; iv += wgt * g.f2.y;
                    Tacc *= (1.0f - a);
                }
            }
        }
    }

    const int pix = pyi * IMG_W + pxi;
    const float mk = __ldg(&mask[pix]);
    const float b0 = __ldg(&bg[0]);
    const float b1 = __ldg(&bg[1]);
    const float b2 = __ldg(&bg[2]);
    out[pix]            = (cr  + Tacc * b0) * mk;
    out[HW + pix]       = (cg  + Tacc * b1) * mk;
    out[2 * HW + pix]   = (cbl + Tacc * b2) * mk;
    out[OFF_INVD + pix] = iv * mk;
}

// ---------------------------------------------------------------------------
extern "C" void kernel_launch(void* const* d_in, const int* in_sizes, int n_in,
                              void* d_out, int out_size)
{
    const float* means3D = (const float*)d_in[0];
    // d_in[1] = means2D (unused by the reference math)
    const float* opac    = (const float*)d_in[2];
    const float* colors  = (const float*)d_in[3];
    const float* scales  = (const float*)d_in[4];
    const float* rots    = (const float*)d_in[5];
    const float* Vm      = (const float*)d_in[6];
    const float* Pm      = (const float*)d_in[7];
    const float* bg      = (const float*)d_in[8];
    const float* mask    = (const float*)d_in[9];
    float* out = (float*)d_out;

    int n = in_sizes[0] / 3;
    if (n > MAXN) n = MAXN;

    fused_raster_kernel<<<dim3(IMG_W / TILE_W, IMG_H / TILE_H), NTHREADS>>>(
        means3D, opac, colors, scales, rots, Vm, Pm, bg, mask, out, n);
}